// round 14
// baseline (speedup 1.0000x reference)
#include <cuda_runtime.h>
#include <cuda_fp16.h>
#include <mma.h>

#define NN 100000
#define EE 1600000
#define BB 256
typedef unsigned long long u64;
typedef unsigned int u32;
using namespace nvcuda;

// ---- static scratch ----
__device__ __align__(16) __half g_xf[NN*64];
__device__ __align__(16) __half g_uf[NN*128];
__device__ __align__(16) __half g_q[NN*128];
__device__ __align__(16) __half g_wimg[327680];
__device__ float g_gsum[BB*128];
__device__ int g_deg[NN], g_rowptr[NN+1], g_cursor[NN], g_col[EE];
__device__ int g_bsum[128], g_boff[128];

__device__ __forceinline__ u32 pack_h2(float a,float b){
  __half2 h=__floats2half2_rn(a,b); return *(u32*)&h;
}
__device__ __forceinline__ void cpa16(void* dst,const void* src){
  u32 d=(u32)__cvta_generic_to_shared(dst);
  asm volatile("cp.async.cg.shared.global [%0],[%1],16;"::"r"(d),"l"(src));
}
__device__ __forceinline__ void cpcommit(){ asm volatile("cp.async.commit_group;":::"memory"); }
template<int N> __device__ __forceinline__ void cpwaitg(){ asm volatile("cp.async.wait_group %0;"::"n"(N):"memory"); }

// ---- CSR ----
__global__ void k_hist(const int* __restrict__ ei){int e=blockIdx.x*blockDim.x+threadIdx.x; if(e<EE)atomicAdd(&g_deg[ei[EE+e]],1);}
__global__ void k_scan1(){
  __shared__ int ws[32];
  int tid=threadIdx.x,lane=tid&31,wid=tid>>5;
  int i=blockIdx.x*1024+tid;
  int v=(i<NN)?g_deg[i]:0;
  int x=v;
#pragma unroll
  for(int o=16;o>0;o>>=1)x+=__shfl_xor_sync(~0u,x,o);
  if(lane==0)ws[wid]=x;
  __syncthreads();
  if(tid==0){int s=0;
#pragma unroll
    for(int w=0;w<32;w++)s+=ws[w];
    g_bsum[blockIdx.x]=s;}
}
__global__ void k_scan2(){
  __shared__ int ws[4];
  int tid=threadIdx.x,lane=tid&31,wid=tid>>5;
  int v=(tid<98)?g_bsum[tid]:0;
  int x=v;
#pragma unroll
  for(int o=1;o<32;o<<=1){int t=__shfl_up_sync(~0u,x,o); if(lane>=o)x+=t;}
  if(lane==31)ws[wid]=x;
  __syncthreads();
  int add=0;
  for(int w=0;w<wid;w++)add+=ws[w];
  if(tid<98)g_boff[tid]=add+x-v;
  if(tid==0)g_rowptr[NN]=EE;
}
__global__ void k_scan3(){
  __shared__ int ws[32];
  int tid=threadIdx.x,lane=tid&31,wid=tid>>5;
  int i=blockIdx.x*1024+tid;
  int v=(i<NN)?g_deg[i]:0;
  int x=v;
#pragma unroll
  for(int o=1;o<32;o<<=1){int t=__shfl_up_sync(~0u,x,o); if(lane>=o)x+=t;}
  if(lane==31)ws[wid]=x;
  __syncthreads();
  if(wid==0){int y=ws[lane];
#pragma unroll
    for(int o=1;o<32;o<<=1){int t=__shfl_up_sync(~0u,y,o); if(lane>=o)y+=t;} ws[lane]=y;}
  __syncthreads();
  if(i<NN){
    int ex=g_boff[blockIdx.x]+x-v+((wid>0)?ws[wid-1]:0);
    g_rowptr[i]=ex; g_cursor[i]=ex;
  }
}
__global__ void k_fill(const int* __restrict__ ei){
  int e=blockIdx.x*blockDim.x+threadIdx.x;
  if(e<EE){int d=ei[EE+e]; int p=atomicAdd(&g_cursor[d],1); g_col[p]=ei[e];}
}

// ---- prep (also zeroes g_deg / g_gsum) ----
__global__ void k_prepx(const float* __restrict__ x){
  int i=blockIdx.x*blockDim.x+threadIdx.x; if(i>=NN*32)return;
  float2 v=((const float2*)x)[i];
  ((u32*)g_xf)[i]=pack_h2(v.x,v.y);
  if(i<NN)g_deg[i]=0;
  if(i<BB*128)g_gsum[i]=0.f;
}
__global__ void k_prepw(const float* __restrict__ Win,const float* __restrict__ W1,
                        const float* __restrict__ W2,const float* __restrict__ gW,
                        const float* __restrict__ oW){
  int gid=blockIdx.x*blockDim.x+threadIdx.x; if(gid>=163840)return;
  const float* src; int idx,K; __half* img;
  if(gid<8192){src=Win;idx=gid;K=64;img=g_wimg;}
  else if(gid<81920){int t=gid-8192;int l=t/24576;idx=t%24576;K=192;src=W1+l*24576;img=g_wimg+16384+l*49152;}
  else if(gid<131072){int t=gid-81920;int l=t/16384;idx=t%16384;K=128;src=W2+l*16384;img=g_wimg+163840+l*32768;}
  else if(gid<147456){idx=gid-131072;K=128;src=gW;img=g_wimg+262144;}
  else {idx=gid-147456;K=128;src=oW;img=g_wimg+294912;}
  float w=src[idx];
  __half h=__float2half_rn(w);
  __half l=__float2half_rn(w-__half2float(h));
  img[idx]=h; img[K*128+idx]=l;
}

// ---- fused gather + GIN pre-act: u = relu((1+eps)q + sum_nbr q + b1) -> fp16 (4-way MLP) ----
__global__ void k_gatheru(const float* __restrict__ eps,int layer,const float* __restrict__ b1){
  int w=(blockIdx.x*blockDim.x+threadIdx.x)>>5, lane=threadIdx.x&31;
  if(w>=NN)return;
  float e1=1.f+eps[layer];
  int s=g_rowptr[w],t=g_rowptr[w+1];
  float4 a0=make_float4(0,0,0,0),a1=a0,a2=a0,a3=a0;
  int e=s;
  auto ld4=[&](int nb)->float4{
    uint2 r=*(const uint2*)(g_q+(size_t)nb*128+lane*4);
    float2 f0=__half22float2(*(__half2*)&r.x);
    float2 f1=__half22float2(*(__half2*)&r.y);
    return make_float4(f0.x,f0.y,f1.x,f1.y);
  };
  for(;e+4<=t;e+=4){
    float4 v0=ld4(g_col[e]),v1=ld4(g_col[e+1]),v2=ld4(g_col[e+2]),v3=ld4(g_col[e+3]);
    a0.x+=v0.x;a0.y+=v0.y;a0.z+=v0.z;a0.w+=v0.w;
    a1.x+=v1.x;a1.y+=v1.y;a1.z+=v1.z;a1.w+=v1.w;
    a2.x+=v2.x;a2.y+=v2.y;a2.z+=v2.z;a2.w+=v2.w;
    a3.x+=v3.x;a3.y+=v3.y;a3.z+=v3.z;a3.w+=v3.w;
  }
  for(;e<t;e++){
    float4 v=ld4(g_col[e]);
    a0.x+=v.x;a0.y+=v.y;a0.z+=v.z;a0.w+=v.w;
  }
  a0.x+=a1.x+a2.x+a3.x; a0.y+=a1.y+a2.y+a3.y;
  a0.z+=a1.z+a2.z+a3.z; a0.w+=a1.w+a2.w+a3.w;
  float4 qo=ld4(w);
  float4 bv=*(const float4*)(b1+lane*4);
  float u0=fmaxf(fmaf(e1,qo.x,a0.x)+bv.x,0.f);
  float u1=fmaxf(fmaf(e1,qo.y,a0.y)+bv.y,0.f);
  float u2=fmaxf(fmaf(e1,qo.z,a0.z)+bv.z,0.f);
  float u3=fmaxf(fmaf(e1,qo.w,a0.w)+bv.w,0.f);
  *(uint2*)(g_uf+(size_t)w*128+lane*4)=make_uint2(pack_h2(u0,u1),pack_h2(u2,u3));
}

// ---- fused GEMM kernels: 64-row tiles, 256 threads, 2 CTAs/SM ----
#define AS_OFF 4096
#define BS_OFF 22528
#define HS_OFF 92160
#define SM_TOT 109568
#define DMID_OFF (BS_OFF+34816)
#define SKA 72
#define SKH 136
#define SNB 136
#define DST 132
#define TM 64
#define APL 4608
#define BPL 8704
#define DS_DW1 0
#define DS_DB1 6144
#define DS_DW2 6176
#define DS_DB2 6432
#define DS_DW3 6440
#define DS_DB3 6448

using FragA=wmma::fragment<wmma::matrix_a,16,16,16,__half,wmma::row_major>;
using FragB=wmma::fragment<wmma::matrix_b,16,16,16,__half,wmma::row_major>;
using FragC=wmma::fragment<wmma::accumulator,16,16,16,float>;

__device__ __forceinline__ void mma_chunk(const __half* Ap,int astr,const __half* Bh,const __half* Bl,
    FragC&a00,FragC&a01,FragC&a10,FragC&a11,int r0,int cw){
#pragma unroll
  for(int kc=0;kc<4;kc++){
    FragA ah0,ah1;
    wmma::load_matrix_sync(ah0,Ap+(size_t)r0*astr+kc*16,astr);
    wmma::load_matrix_sync(ah1,Ap+(size_t)(r0+16)*astr+kc*16,astr);
    FragB bh0,bh1,bl0,bl1;
    wmma::load_matrix_sync(bh0,Bh+(size_t)(kc*16)*SNB+cw,SNB);
    wmma::load_matrix_sync(bh1,Bh+(size_t)(kc*16)*SNB+cw+16,SNB);
    wmma::load_matrix_sync(bl0,Bl+(size_t)(kc*16)*SNB+cw,SNB);
    wmma::load_matrix_sync(bl1,Bl+(size_t)(kc*16)*SNB+cw+16,SNB);
    wmma::mma_sync(a00,ah0,bh0,a00); wmma::mma_sync(a00,ah0,bl0,a00);
    wmma::mma_sync(a01,ah0,bh1,a01); wmma::mma_sync(a01,ah0,bl1,a01);
    wmma::mma_sync(a10,ah1,bh0,a10); wmma::mma_sync(a10,ah1,bl0,a10);
    wmma::mma_sync(a11,ah1,bh1,a11); wmma::mma_sync(a11,ah1,bl1,a11);
  }
}
__device__ __forceinline__ void acc_store(float* D,FragC&a00,FragC&a01,FragC&a10,FragC&a11,int r0,int cw){
  wmma::store_matrix_sync(D+(size_t)r0*DST+cw,a00,DST,wmma::mem_row_major);
  wmma::store_matrix_sync(D+(size_t)r0*DST+cw+16,a01,DST,wmma::mem_row_major);
  wmma::store_matrix_sync(D+(size_t)(r0+16)*DST+cw,a10,DST,wmma::mem_row_major);
  wmma::store_matrix_sync(D+(size_t)(r0+16)*DST+cw+16,a11,DST,wmma::mem_row_major);
}
__device__ __forceinline__ void stage_B(const __half* ws,int KT,int c,int buf,unsigned char* smx,int tid){
  __half* Bs=(__half*)(smx+BS_OFF);
  for(int i=tid;i<2048;i+=256){
    int pl=i>>10,j=i&1023,kk=j>>4,u=j&15;
    cpa16(Bs+(size_t)(buf*2+pl)*BPL+kk*SNB+u*8,
          ws+(size_t)pl*KT*128+(size_t)(c*64+kk)*128+u*8);
  }
}
__device__ __forceinline__ void stage_Ag(const __half* p0,int K0,int c,int buf,unsigned char* smx,int tid,int base){
  __half* As=(__half*)(smx+AS_OFF);
  for(int i=tid;i<512;i+=256){
    int row=i>>3,u=i&7;
    int gc=c*64+u*8,node=base+row;
    __half* dst=As+(size_t)buf*APL+row*SKA+u*8;
    if(node<NN) cpa16(dst,p0+(size_t)node*K0+gc);
    else *(uint4*)dst=make_uint4(0,0,0,0);
  }
}
template<int MODE>
__device__ __forceinline__ void epi_to_Hs(unsigned char* smx,const float* bias,const float* lg,const float* lb,int tid){
  float* D=(float*)(smx+DMID_OFF);
  float* sr1=(float*)(smx+512); float* sr2=(float*)(smx+1536);
  __half* Hs=(__half*)(smx+HS_OFF);
  int C0=(tid>>6)*32,R=tid&63;
  float v[32];
  u32 hw[16];
  if(MODE==0){
#pragma unroll
    for(int j=0;j<32;j++)v[j]=fmaxf(D[(size_t)R*DST+C0+j]+bias[C0+j],0.f);
#pragma unroll
    for(int j=0;j<16;j++)hw[j]=pack_h2(v[2*j],v[2*j+1]);
  }else{
    float s=0.f,s2=0.f;
#pragma unroll
    for(int j=0;j<32;j++){v[j]=D[(size_t)R*DST+C0+j]+bias[C0+j]; s+=v[j]; s2+=v[j]*v[j];}
    sr1[(tid>>6)*64+R]=s; sr2[(tid>>6)*64+R]=s2;
    __syncthreads();
    s=sr1[R]+sr1[64+R]+sr1[128+R]+sr1[192+R];
    s2=sr2[R]+sr2[64+R]+sr2[128+R]+sr2[192+R];
    float mu=s*(1.f/128.f), var=fmaxf(s2*(1.f/128.f)-mu*mu,0.f), rs=rsqrtf(var+1e-5f);
#pragma unroll
    for(int j=0;j<16;j++){
      float n0=(v[2*j]-mu)*rs*lg[C0+2*j]+lb[C0+2*j];
      float n1=(v[2*j+1]-mu)*rs*lg[C0+2*j+1]+lb[C0+2*j+1];
      n0=(n0>0.f)?n0:expm1f(n0);
      n1=(n1>0.f)?n1:expm1f(n1);
      hw[j]=pack_h2(n0,n1);
    }
  }
  uint4* oh=(uint4*)(Hs+(size_t)R*SKH+C0);
#pragma unroll
  for(int j=0;j<4;j++)oh[j]=((uint4*)hw)[j];
  __syncthreads();
}
// GEMM1 (K=192): chunk0 (A=x into As buf0, B into Bs buf0) PRESTAGED+committed by caller.
__device__ __forceinline__ void gemm1_to_q(int woff,unsigned char* smx,int tid,int base){
  __half* As=(__half*)(smx+AS_OFF);
  __half* Bs=(__half*)(smx+BS_OFF);
  __half* Hs=(__half*)(smx+HS_OFF);
  float* D=(float*)(smx+AS_OFF);
  const __half* ws=g_wimg+woff;
  int wid=tid>>5;
  int r0=(wid&1)*32, cw=(wid>>1)*32;
  FragC a00,a01,a10,a11;
  wmma::fill_fragment(a00,0.f); wmma::fill_fragment(a01,0.f);
  wmma::fill_fragment(a10,0.f); wmma::fill_fragment(a11,0.f);
  for(int c=0;c<3;c++){
    int buf=c&1;
    if(c+1<3){ stage_B(ws,192,c+1,buf^1,smx,tid); cpcommit(); cpwaitg<1>(); }
    else cpwaitg<0>();
    __syncthreads();
    const __half* Ap; int astr;
    if(c==0){Ap=As; astr=SKA;} else {Ap=Hs+(c-1)*64; astr=SKH;}
    mma_chunk(Ap,astr,Bs+(size_t)(buf*2)*BPL,Bs+(size_t)(buf*2+1)*BPL,a00,a01,a10,a11,r0,cw);
    __syncthreads();
  }
  acc_store(D,a00,a01,a10,a11,r0,cw);
  __syncthreads();
  int C0=(tid>>6)*32,R=tid&63,node=base+R;
  if(node<NN){
    u32 hw[16];
#pragma unroll
    for(int j=0;j<16;j++)hw[j]=pack_h2(D[(size_t)R*DST+C0+2*j],D[(size_t)R*DST+C0+2*j+1]);
    uint4* oq=(uint4*)(g_q+(size_t)node*128+C0);
#pragma unroll
    for(int j=0;j<4;j++)oq[j]=((uint4*)hw)[j];
  }
  __syncthreads();
}
// K=128 GEMM, A from global (u) or Hs, into D_MID. PRE=1: chunk0 prestaged+committed by caller.
template<int AHS,int PRE>
__device__ __forceinline__ void gemm128_mid(int woff,const __half* p0,unsigned char* smx,int tid,int base){
  __half* As=(__half*)(smx+AS_OFF);
  __half* Bs=(__half*)(smx+BS_OFF);
  __half* Hs=(__half*)(smx+HS_OFF);
  float* D=(float*)(smx+DMID_OFF);
  const __half* ws=g_wimg+woff;
  int wid=tid>>5;
  int r0=(wid&1)*32, cw=(wid>>1)*32;
  FragC a00,a01,a10,a11;
  wmma::fill_fragment(a00,0.f); wmma::fill_fragment(a01,0.f);
  wmma::fill_fragment(a10,0.f); wmma::fill_fragment(a11,0.f);
  if(!PRE){
    stage_B(ws,128,0,0,smx,tid);
    if(!AHS) stage_Ag(p0,128,0,0,smx,tid,base);
    cpcommit();
  }
  stage_B(ws,128,1,1,smx,tid);
  if(!AHS) stage_Ag(p0,128,1,1,smx,tid,base);
  cpcommit();
  for(int c=0;c<2;c++){
    if(c==0) cpwaitg<1>(); else cpwaitg<0>();
    __syncthreads();
    const __half* Ap; int astr;
    if(AHS){Ap=Hs+c*64; astr=SKH;} else {Ap=As+(size_t)c*APL; astr=SKA;}
    mma_chunk(Ap,astr,Bs+(size_t)(c*2)*BPL,Bs+(size_t)(c*2+1)*BPL,a00,a01,a10,a11,r0,cw);
    __syncthreads();
  }
  acc_store(D,a00,a01,a10,a11,r0,cw);
  __syncthreads();
}

// fused: encoder + GEMM1 layer0
__global__ void __launch_bounds__(256,2) k_encg1(const float* __restrict__ b_in){
  extern __shared__ unsigned char smx[];
  int tid=threadIdx.x;
  int base=blockIdx.x*TM;
  int wid=tid>>5;
  int r0=(wid&1)*32, cw=(wid>>1)*32;
  __half* As=(__half*)(smx+AS_OFF);
  __half* Bs=(__half*)(smx+BS_OFF);
  float* D=(float*)(smx+DMID_OFF);
  stage_B(g_wimg,64,0,0,smx,tid);
  stage_Ag(g_xf,64,0,0,smx,tid,base);
  cpcommit(); cpwaitg<0>();
  __syncthreads();
  {
    FragC a00,a01,a10,a11;
    wmma::fill_fragment(a00,0.f); wmma::fill_fragment(a01,0.f);
    wmma::fill_fragment(a10,0.f); wmma::fill_fragment(a11,0.f);
    mma_chunk(As,SKA,Bs,Bs+BPL,a00,a01,a10,a11,r0,cw);
    __syncthreads();
    acc_store(D,a00,a01,a10,a11,r0,cw);
    __syncthreads();
  }
  // prestage gemm1 chunk0 (x tile + B c0 -> buf0), hidden under the relu epilogue
  stage_Ag(g_xf,64,0,0,smx,tid,base);
  stage_B(g_wimg+16384,192,0,0,smx,tid);
  cpcommit();
  epi_to_Hs<0>(smx,b_in,nullptr,nullptr,tid);
  gemm1_to_q(16384,smx,tid,base);
}

// fused: GEMM2 layer l + GEMM1 layer l+1
__global__ void __launch_bounds__(256,2) k_g2g1(int woff2,int woff1,
    const float* __restrict__ b2,const float* __restrict__ lg,const float* __restrict__ lb){
  extern __shared__ unsigned char smx[];
  int tid=threadIdx.x;
  int base=blockIdx.x*TM;
  gemm128_mid<0,0>(woff2,g_uf,smx,tid,base);
  // prestage gemm1 chunk0 under the LN+ELU epilogue
  stage_Ag(g_xf,64,0,0,smx,tid,base);
  stage_B(g_wimg+woff1,192,0,0,smx,tid);
  cpcommit();
  epi_to_Hs<1>(smx,b2,lg,lb,tid);
  gemm1_to_q(woff1,smx,tid,base);
}

// fused: GEMM2 layer2 + graphemb(LN+pool) + nodeout(LN+decoder)
__global__ void __launch_bounds__(256,2) k_g2fin(int woff2,
    const float* __restrict__ b2,const float* __restrict__ lg2,const float* __restrict__ lb2,
    const int* __restrict__ bidx,
    const float* __restrict__ gb,const float* __restrict__ glg,const float* __restrict__ glb,
    const float* __restrict__ ob,const float* __restrict__ lfg,const float* __restrict__ lfb,
    const float* __restrict__ x,
    const float* __restrict__ dW1,const float* __restrict__ db1,
    const float* __restrict__ dW2,const float* __restrict__ db2,
    const float* __restrict__ dW3,const float* __restrict__ db3,
    float* __restrict__ outp){
  extern __shared__ unsigned char smx[];
  int tid=threadIdx.x,lane=tid&31,wid=tid>>5;
  int base=blockIdx.x*TM;
  int* sbid=(int*)smx;
  float* sr1=(float*)(smx+512); float* sr2=(float*)(smx+1536);
  __half* Hs=(__half*)(smx+HS_OFF);
  if(tid<TM){int nd=base+tid; sbid[tid]=(nd<NN)?bidx[nd]:-1;}
  gemm128_mid<0,0>(woff2,g_uf,smx,tid,base);
  // prestage graphemb B c0 under the LN+ELU epilogue
  stage_B(g_wimg+262144,128,0,0,smx,tid);
  cpcommit();
  epi_to_Hs<1>(smx,b2,lg2,lb2,tid);
  // graphemb: A=Hs (chunk0 prestaged)
  gemm128_mid<1,1>(262144,nullptr,smx,tid,base);
  // prestage nodeout B c0 under the graphemb LN+pool
  stage_B(g_wimg+294912,128,0,0,smx,tid);
  cpcommit();
  {
    float* Dm=(float*)(smx+DMID_OFF);
    int C0=(tid>>6)*32,R=tid&63;
    float v[32]; float s=0.f,s2=0.f;
#pragma unroll
    for(int j=0;j<32;j++){v[j]=fmaxf(Dm[(size_t)R*DST+C0+j]+gb[C0+j],0.f); s+=v[j]; s2+=v[j]*v[j];}
    sr1[(tid>>6)*64+R]=s; sr2[(tid>>6)*64+R]=s2;
    __syncthreads();
    s=sr1[R]+sr1[64+R]+sr1[128+R]+sr1[192+R];
    s2=sr2[R]+sr2[64+R]+sr2[128+R]+sr2[192+R];
    float mu=s*(1.f/128.f), var=fmaxf(s2*(1.f/128.f)-mu*mu,0.f), rs=rsqrtf(var+1e-5f);
#pragma unroll
    for(int j=0;j<32;j++)Dm[(size_t)R*DST+C0+j]=(v[j]-mu)*rs*glg[C0+j]+glb[C0+j];
    __syncthreads();
    if(tid<128){
      int col=tid; float a=0.f; int cur=-1;
      for(int r=0;r<TM;r++){
        int bi=sbid[r];
        if(bi!=cur){ if(cur>=0)atomicAdd(&g_gsum[cur*128+col],a); a=0.f; cur=bi; }
        if(bi>=0)a+=Dm[(size_t)r*DST+col];
      }
      if(cur>=0)atomicAdd(&g_gsum[cur*128+col],a);
    }
    __syncthreads();
  }
  // nodeout: A=Hs (chunk0 prestaged)
  gemm128_mid<1,1>(294912,nullptr,smx,tid,base);
  {
    float* Dm=(float*)(smx+DMID_OFF);
    int C0=(tid>>6)*32,R=tid&63;
    float v[32]; float s=0.f,s2=0.f;
#pragma unroll
    for(int j=0;j<32;j++){v[j]=fmaxf(Dm[(size_t)R*DST+C0+j]+ob[C0+j],0.f); s+=v[j]; s2+=v[j]*v[j];}
    sr1[(tid>>6)*64+R]=s; sr2[(tid>>6)*64+R]=s2;
    __syncthreads();
    s=sr1[R]+sr1[64+R]+sr1[128+R]+sr1[192+R];
    s2=sr2[R]+sr2[64+R]+sr2[128+R]+sr2[192+R];
    float mu=s*(1.f/128.f), var=fmaxf(s2*(1.f/128.f)-mu*mu,0.f), rs=rsqrtf(var+1e-5f);
#pragma unroll
    for(int j=0;j<32;j++)Dm[(size_t)R*DST+C0+j]=(v[j]-mu)*rs*lfg[C0+j]+lfb[C0+j];
    // decoder: xsh (fp32 x tile) into Hs region (dead), dsh in Bs region
    float* xsh=(float*)(smx+HS_OFF);
    float* dsh=(float*)(smx+BS_OFF);
    for(int i=tid;i<4096;i+=256){int r=i>>6,k=i&63;int nd=base+r;xsh[i]=(nd<NN)?x[(size_t)nd*64+k]:0.f;}
    for(int i=tid;i<6144;i+=256)dsh[DS_DW1+i]=dW1[i];
    if(tid<32)dsh[DS_DB1+tid]=db1[tid];
    if(tid<256)dsh[DS_DW2+tid]=dW2[tid];
    if(tid<8){dsh[DS_DB2+tid]=db2[tid];dsh[DS_DW3+tid]=dW3[tid];}
    if(tid==0)dsh[DS_DB3]=db3[0];
    __syncthreads();
    int j=lane, rr0=wid*8;
    for(int i=0;i<8;i++){
      int row=rr0+i, nd=base+row;
      float s1=dsh[DS_DB1+j];
      const float* xr=xsh+(size_t)row*64;
      const float* nr=Dm+(size_t)row*DST;
#pragma unroll 4
      for(int k=0;k<64;k++)s1=fmaf(xr[k],dsh[DS_DW1+k*32+j],s1);
#pragma unroll 4
      for(int k=0;k<128;k++)s1=fmaf(nr[k],dsh[DS_DW1+(64+k)*32+j],s1);
      s1=fmaxf(s1,0.f);
      float t2[8];
#pragma unroll
      for(int m=0;m<8;m++)t2[m]=s1*dsh[DS_DW2+j*8+m];
#pragma unroll
      for(int o=16;o>0;o>>=1)
#pragma unroll
        for(int m=0;m<8;m++)t2[m]+=__shfl_xor_sync(~0u,t2[m],o);
      float out=dsh[DS_DB3];
#pragma unroll
      for(int m=0;m<8;m++)out=fmaf(fmaxf(t2[m]+dsh[DS_DB2+m],0.f),dsh[DS_DW3+m],out);
      if(j==0&&nd<NN)outp[nd]=out;
    }
  }
}

// ---- graph-level MLP ----
__device__ __forceinline__ int lbound(const int* __restrict__ a,int n,int v){
  int lo=0,hi=n;
  while(lo<hi){int m=(lo+hi)>>1; if(a[m]<v)lo=m+1; else hi=m;}
  return lo;
}
__global__ void k_gmlp(const int* __restrict__ bidx,
    const float* __restrict__ gW1,const float* __restrict__ gb1,
    const float* __restrict__ gW2,const float* __restrict__ gb2,
    const float* __restrict__ gW3,const float* __restrict__ gb3,
    float* __restrict__ outp){
  int tid=threadIdx.x,lane=tid&31;
  int g=blockIdx.x*8+(tid>>5);
  int lo=lbound(bidx,NN,g),hi=lbound(bidx,NN,g+1);
  float inv=1.f/fmaxf((float)(hi-lo),1.f);
  float s1=gb1[lane];
  for(int k=0;k<128;k++)s1=fmaf(g_gsum[g*128+k]*inv,gW1[k*32+lane],s1);
  s1=fmaxf(s1,0.f);
  float t2[8];
#pragma unroll
  for(int m=0;m<8;m++)t2[m]=s1*gW2[lane*8+m];
#pragma unroll
  for(int o=16;o>0;o>>=1)
#pragma unroll
    for(int m=0;m<8;m++)t2[m]+=__shfl_xor_sync(~0u,t2[m],o);
  float out=gb3[0];
#pragma unroll
  for(int m=0;m<8;m++)out=fmaf(fmaxf(t2[m]+gb2[m],0.f),gW3[m],out);
  if(lane==0)outp[NN+g]=out;
}

extern "C" void kernel_launch(void* const* d_in,const int* in_sizes,int n_in,
                              void* d_out,int out_size){
  (void)in_sizes;(void)n_in;(void)out_size;
  const float* x   =(const float*)d_in[0];
  const int*   ei  =(const int*)  d_in[1];
  const int*   bidx=(const int*)  d_in[2];
  const float* W_in=(const float*)d_in[3];
  const float* b_in=(const float*)d_in[4];
  const float* eps =(const float*)d_in[5];
  const float* mW1 =(const float*)d_in[6];
  const float* mb1 =(const float*)d_in[7];
  const float* mW2 =(const float*)d_in[8];
  const float* mb2 =(const float*)d_in[9];
  const float* lng =(const float*)d_in[10];
  const float* lnb =(const float*)d_in[11];
  const float* oW  =(const float*)d_in[12];
  const float* ob  =(const float*)d_in[13];
  const float* lfg =(const float*)d_in[14];
  const float* lfb =(const float*)d_in[15];
  const float* gW  =(const float*)d_in[16];
  const float* gb  =(const float*)d_in[17];
  const float* glg =(const float*)d_in[18];
  const float* glb =(const float*)d_in[19];
  const float* dW1 =(const float*)d_in[20];
  const float* db1 =(const float*)d_in[21];
  const float* dW2 =(const float*)d_in[22];
  const float* db2 =(const float*)d_in[23];
  const float* dW3 =(const float*)d_in[24];
  const float* db3 =(const float*)d_in[25];
  const float* gW1 =(const float*)d_in[26];
  const float* gb1 =(const float*)d_in[27];
  const float* gW2 =(const float*)d_in[28];
  const float* gb2 =(const float*)d_in[29];
  const float* gW3 =(const float*)d_in[30];
  const float* gb3 =(const float*)d_in[31];
  float* outp=(float*)d_out;

  const int NG=(NN+TM-1)/TM;   // 1563
  cudaFuncSetAttribute((const void*)k_encg1,cudaFuncAttributeMaxDynamicSharedMemorySize,SM_TOT);
  cudaFuncSetAttribute((const void*)k_g2g1, cudaFuncAttributeMaxDynamicSharedMemorySize,SM_TOT);
  cudaFuncSetAttribute((const void*)k_g2fin,cudaFuncAttributeMaxDynamicSharedMemorySize,SM_TOT);

  k_prepx<<<12500,256>>>(x);                                             //0 (+zero)
  k_prepw<<<640,256>>>(W_in,mW1,mW2,gW,oW);                              //1
  k_encg1<<<NG,256,SM_TOT>>>(b_in);                                      //2
  k_hist<<<6250,256>>>(ei);                                              //3
  k_scan1<<<98,1024>>>();                                                //4
  k_scan2<<<1,128>>>();                                                  //5
  k_scan3<<<98,1024>>>();                                                //6
  k_fill<<<6250,256>>>(ei);                                              //7

  for(int l=0;l<2;l++){
    k_gatheru<<<12500,256>>>(eps,l,mb1+l*128);
    k_g2g1<<<NG,256,SM_TOT>>>(163840+l*32768,16384+(l+1)*49152,
        mb2+l*128,lng+l*128,lnb+l*128);
  }
  k_gatheru<<<12500,256>>>(eps,2,mb1+256);
  k_g2fin<<<NG,256,SM_TOT>>>(163840+2*32768,mb2+256,lng+256,lnb+256,bidx,
      gb,glg,glb,ob,lfg,lfb,x,dW1,db1,dW2,db2,dW3,db3,outp);
  k_gmlp<<<32,256>>>(bidx,gW1,gb1,gW2,gb2,gW3,gb3,outp);
}

// round 15
// speedup vs baseline: 1.0167x; 1.0167x over previous
#include <cuda_runtime.h>
#include <cuda_fp16.h>
#include <mma.h>

#define NN 100000
#define EE 1600000
#define BB 256
typedef unsigned long long u64;
typedef unsigned int u32;
using namespace nvcuda;

// ---- static scratch ----
__device__ __align__(16) __half g_xf[NN*64];
__device__ __align__(16) __half g_uf[NN*128];
__device__ __align__(16) __half g_q[NN*128];
__device__ __align__(16) __half g_wimg[327680];
__device__ float g_gsum[BB*128];
__device__ int g_deg[NN], g_rowptr[NN+1], g_cursor[NN], g_col[EE];
__device__ int g_bsum[128], g_boff[128];

__device__ __forceinline__ u32 pack_h2(float a,float b){
  __half2 h=__floats2half2_rn(a,b); return *(u32*)&h;
}
__device__ __forceinline__ void cpa16(void* dst,const void* src){
  u32 d=(u32)__cvta_generic_to_shared(dst);
  asm volatile("cp.async.cg.shared.global [%0],[%1],16;"::"r"(d),"l"(src));
}
__device__ __forceinline__ void cpcommit(){ asm volatile("cp.async.commit_group;":::"memory"); }
template<int N> __device__ __forceinline__ void cpwaitg(){ asm volatile("cp.async.wait_group %0;"::"n"(N):"memory"); }

// ---- CSR ----
__global__ void k_hist(const int* __restrict__ ei){int e=blockIdx.x*blockDim.x+threadIdx.x; if(e<EE)atomicAdd(&g_deg[ei[EE+e]],1);}
__global__ void k_scan1(){
  __shared__ int ws[32];
  int tid=threadIdx.x,lane=tid&31,wid=tid>>5;
  int i=blockIdx.x*1024+tid;
  int v=(i<NN)?g_deg[i]:0;
  int x=v;
#pragma unroll
  for(int o=16;o>0;o>>=1)x+=__shfl_xor_sync(~0u,x,o);
  if(lane==0)ws[wid]=x;
  __syncthreads();
  if(tid==0){int s=0;
#pragma unroll
    for(int w=0;w<32;w++)s+=ws[w];
    g_bsum[blockIdx.x]=s;}
}
__global__ void k_scan2(){
  __shared__ int ws[4];
  int tid=threadIdx.x,lane=tid&31,wid=tid>>5;
  int v=(tid<98)?g_bsum[tid]:0;
  int x=v;
#pragma unroll
  for(int o=1;o<32;o<<=1){int t=__shfl_up_sync(~0u,x,o); if(lane>=o)x+=t;}
  if(lane==31)ws[wid]=x;
  __syncthreads();
  int add=0;
  for(int w=0;w<wid;w++)add+=ws[w];
  if(tid<98)g_boff[tid]=add+x-v;
  if(tid==0)g_rowptr[NN]=EE;
}
__global__ void k_scan3(){
  __shared__ int ws[32];
  int tid=threadIdx.x,lane=tid&31,wid=tid>>5;
  int i=blockIdx.x*1024+tid;
  int v=(i<NN)?g_deg[i]:0;
  int x=v;
#pragma unroll
  for(int o=1;o<32;o<<=1){int t=__shfl_up_sync(~0u,x,o); if(lane>=o)x+=t;}
  if(lane==31)ws[wid]=x;
  __syncthreads();
  if(wid==0){int y=ws[lane];
#pragma unroll
    for(int o=1;o<32;o<<=1){int t=__shfl_up_sync(~0u,y,o); if(lane>=o)y+=t;} ws[lane]=y;}
  __syncthreads();
  if(i<NN){
    int ex=g_boff[blockIdx.x]+x-v+((wid>0)?ws[wid-1]:0);
    g_rowptr[i]=ex; g_cursor[i]=ex;
  }
}
__global__ void k_fill(const int* __restrict__ ei){
  int e=blockIdx.x*blockDim.x+threadIdx.x;
  if(e<EE){int d=ei[EE+e]; int p=atomicAdd(&g_cursor[d],1); g_col[p]=ei[e];}
}

// ---- prep (also zeroes g_deg / g_gsum) ----
__global__ void k_prepx(const float* __restrict__ x){
  int i=blockIdx.x*blockDim.x+threadIdx.x; if(i>=NN*32)return;
  float2 v=((const float2*)x)[i];
  ((u32*)g_xf)[i]=pack_h2(v.x,v.y);
  if(i<NN)g_deg[i]=0;
  if(i<BB*128)g_gsum[i]=0.f;
}
__global__ void k_prepw(const float* __restrict__ Win,const float* __restrict__ W1,
                        const float* __restrict__ W2,const float* __restrict__ gW,
                        const float* __restrict__ oW){
  int gid=blockIdx.x*blockDim.x+threadIdx.x; if(gid>=163840)return;
  const float* src; int idx,K; __half* img;
  if(gid<8192){src=Win;idx=gid;K=64;img=g_wimg;}
  else if(gid<81920){int t=gid-8192;int l=t/24576;idx=t%24576;K=192;src=W1+l*24576;img=g_wimg+16384+l*49152;}
  else if(gid<131072){int t=gid-81920;int l=t/16384;idx=t%16384;K=128;src=W2+l*16384;img=g_wimg+163840+l*32768;}
  else if(gid<147456){idx=gid-131072;K=128;src=gW;img=g_wimg+262144;}
  else {idx=gid-147456;K=128;src=oW;img=g_wimg+294912;}
  float w=src[idx];
  __half h=__float2half_rn(w);
  __half l=__float2half_rn(w-__half2float(h));
  img[idx]=h; img[K*128+idx]=l;
}

// ---- fused gather + GIN pre-act: u = relu((1+eps)q + sum_nbr q + b1) -> fp16 (4-way MLP) ----
__global__ void k_gatheru(const float* __restrict__ eps,int layer,const float* __restrict__ b1){
  int w=(blockIdx.x*blockDim.x+threadIdx.x)>>5, lane=threadIdx.x&31;
  if(w>=NN)return;
  float e1=1.f+eps[layer];
  int s=g_rowptr[w],t=g_rowptr[w+1];
  float4 a0=make_float4(0,0,0,0),a1=a0,a2=a0,a3=a0;
  int e=s;
  auto ld4=[&](int nb)->float4{
    uint2 r=*(const uint2*)(g_q+(size_t)nb*128+lane*4);
    float2 f0=__half22float2(*(__half2*)&r.x);
    float2 f1=__half22float2(*(__half2*)&r.y);
    return make_float4(f0.x,f0.y,f1.x,f1.y);
  };
  for(;e+4<=t;e+=4){
    float4 v0=ld4(g_col[e]),v1=ld4(g_col[e+1]),v2=ld4(g_col[e+2]),v3=ld4(g_col[e+3]);
    a0.x+=v0.x;a0.y+=v0.y;a0.z+=v0.z;a0.w+=v0.w;
    a1.x+=v1.x;a1.y+=v1.y;a1.z+=v1.z;a1.w+=v1.w;
    a2.x+=v2.x;a2.y+=v2.y;a2.z+=v2.z;a2.w+=v2.w;
    a3.x+=v3.x;a3.y+=v3.y;a3.z+=v3.z;a3.w+=v3.w;
  }
  for(;e<t;e++){
    float4 v=ld4(g_col[e]);
    a0.x+=v.x;a0.y+=v.y;a0.z+=v.z;a0.w+=v.w;
  }
  a0.x+=a1.x+a2.x+a3.x; a0.y+=a1.y+a2.y+a3.y;
  a0.z+=a1.z+a2.z+a3.z; a0.w+=a1.w+a2.w+a3.w;
  float4 qo=ld4(w);
  float4 bv=*(const float4*)(b1+lane*4);
  float u0=fmaxf(fmaf(e1,qo.x,a0.x)+bv.x,0.f);
  float u1=fmaxf(fmaf(e1,qo.y,a0.y)+bv.y,0.f);
  float u2=fmaxf(fmaf(e1,qo.z,a0.z)+bv.z,0.f);
  float u3=fmaxf(fmaf(e1,qo.w,a0.w)+bv.w,0.f);
  *(uint2*)(g_uf+(size_t)w*128+lane*4)=make_uint2(pack_h2(u0,u1),pack_h2(u2,u3));
}

// ---- fused GEMM kernels: 64-row tiles, 256 threads, 2 CTAs/SM ----
#define AS_OFF 4096
#define BS_OFF 22528
#define HS_OFF 92160
#define SM_TOT 109568
#define DMID_OFF (BS_OFF+34816)
#define SKA 72
#define SKH 136
#define SNB 136
#define DST 132
#define TM 64
#define APL 4608
#define BPL 8704
#define DS_DW1 0
#define DS_DB1 6144
#define DS_DW2 6176
#define DS_DB2 6432
#define DS_DW3 6440
#define DS_DB3 6448

using FragA=wmma::fragment<wmma::matrix_a,16,16,16,__half,wmma::row_major>;
using FragB=wmma::fragment<wmma::matrix_b,16,16,16,__half,wmma::row_major>;
using FragC=wmma::fragment<wmma::accumulator,16,16,16,float>;

__device__ __forceinline__ void mma_chunk(const __half* Ap,int astr,const __half* Bh,const __half* Bl,
    FragC&a00,FragC&a01,FragC&a10,FragC&a11,int r0,int cw){
#pragma unroll
  for(int kc=0;kc<4;kc++){
    FragA ah0,ah1;
    wmma::load_matrix_sync(ah0,Ap+(size_t)r0*astr+kc*16,astr);
    wmma::load_matrix_sync(ah1,Ap+(size_t)(r0+16)*astr+kc*16,astr);
    FragB bh0,bh1,bl0,bl1;
    wmma::load_matrix_sync(bh0,Bh+(size_t)(kc*16)*SNB+cw,SNB);
    wmma::load_matrix_sync(bh1,Bh+(size_t)(kc*16)*SNB+cw+16,SNB);
    wmma::load_matrix_sync(bl0,Bl+(size_t)(kc*16)*SNB+cw,SNB);
    wmma::load_matrix_sync(bl1,Bl+(size_t)(kc*16)*SNB+cw+16,SNB);
    wmma::mma_sync(a00,ah0,bh0,a00); wmma::mma_sync(a00,ah0,bl0,a00);
    wmma::mma_sync(a01,ah0,bh1,a01); wmma::mma_sync(a01,ah0,bl1,a01);
    wmma::mma_sync(a10,ah1,bh0,a10); wmma::mma_sync(a10,ah1,bl0,a10);
    wmma::mma_sync(a11,ah1,bh1,a11); wmma::mma_sync(a11,ah1,bl1,a11);
  }
}
__device__ __forceinline__ void acc_store(float* D,FragC&a00,FragC&a01,FragC&a10,FragC&a11,int r0,int cw){
  wmma::store_matrix_sync(D+(size_t)r0*DST+cw,a00,DST,wmma::mem_row_major);
  wmma::store_matrix_sync(D+(size_t)r0*DST+cw+16,a01,DST,wmma::mem_row_major);
  wmma::store_matrix_sync(D+(size_t)(r0+16)*DST+cw,a10,DST,wmma::mem_row_major);
  wmma::store_matrix_sync(D+(size_t)(r0+16)*DST+cw+16,a11,DST,wmma::mem_row_major);
}
__device__ __forceinline__ void stage_B(const __half* ws,int KT,int c,int buf,unsigned char* smx,int tid){
  __half* Bs=(__half*)(smx+BS_OFF);
  for(int i=tid;i<2048;i+=256){
    int pl=i>>10,j=i&1023,kk=j>>4,u=j&15;
    cpa16(Bs+(size_t)(buf*2+pl)*BPL+kk*SNB+u*8,
          ws+(size_t)pl*KT*128+(size_t)(c*64+kk)*128+u*8);
  }
}
__device__ __forceinline__ void stage_Ag(const __half* p0,int K0,int c,int buf,unsigned char* smx,int tid,int base){
  __half* As=(__half*)(smx+AS_OFF);
  for(int i=tid;i<512;i+=256){
    int row=i>>3,u=i&7;
    int gc=c*64+u*8,node=base+row;
    __half* dst=As+(size_t)buf*APL+row*SKA+u*8;
    if(node<NN) cpa16(dst,p0+(size_t)node*K0+gc);
    else *(uint4*)dst=make_uint4(0,0,0,0);
  }
}
template<int MODE>
__device__ __forceinline__ void epi_to_Hs(unsigned char* smx,const float* bias,const float* lg,const float* lb,int tid){
  float* D=(float*)(smx+DMID_OFF);
  float* sr1=(float*)(smx+512); float* sr2=(float*)(smx+1536);
  __half* Hs=(__half*)(smx+HS_OFF);
  int C0=(tid>>6)*32,R=tid&63;
  float v[32];
  u32 hw[16];
  if(MODE==0){
#pragma unroll
    for(int j=0;j<32;j++)v[j]=fmaxf(D[(size_t)R*DST+C0+j]+bias[C0+j],0.f);
#pragma unroll
    for(int j=0;j<16;j++)hw[j]=pack_h2(v[2*j],v[2*j+1]);
  }else{
    float s=0.f,s2=0.f;
#pragma unroll
    for(int j=0;j<32;j++){v[j]=D[(size_t)R*DST+C0+j]+bias[C0+j]; s+=v[j]; s2+=v[j]*v[j];}
    sr1[(tid>>6)*64+R]=s; sr2[(tid>>6)*64+R]=s2;
    __syncthreads();
    s=sr1[R]+sr1[64+R]+sr1[128+R]+sr1[192+R];
    s2=sr2[R]+sr2[64+R]+sr2[128+R]+sr2[192+R];
    float mu=s*(1.f/128.f), var=fmaxf(s2*(1.f/128.f)-mu*mu,0.f), rs=rsqrtf(var+1e-5f);
#pragma unroll
    for(int j=0;j<16;j++){
      float n0=(v[2*j]-mu)*rs*lg[C0+2*j]+lb[C0+2*j];
      float n1=(v[2*j+1]-mu)*rs*lg[C0+2*j+1]+lb[C0+2*j+1];
      n0=(n0>0.f)?n0:expm1f(n0);
      n1=(n1>0.f)?n1:expm1f(n1);
      hw[j]=pack_h2(n0,n1);
    }
  }
  uint4* oh=(uint4*)(Hs+(size_t)R*SKH+C0);
#pragma unroll
  for(int j=0;j<4;j++)oh[j]=((uint4*)hw)[j];
  __syncthreads();
}
// GEMM1 (K=192): A chunk0 = As buf0 (x), chunks 1,2 = Hs. D -> g_q
__device__ __forceinline__ void gemm1_to_q(int woff,unsigned char* smx,int tid,int base){
  __half* As=(__half*)(smx+AS_OFF);
  __half* Bs=(__half*)(smx+BS_OFF);
  __half* Hs=(__half*)(smx+HS_OFF);
  float* D=(float*)(smx+AS_OFF);
  const __half* ws=g_wimg+woff;
  int wid=tid>>5;
  int r0=(wid&1)*32, cw=(wid>>1)*32;
  FragC a00,a01,a10,a11;
  wmma::fill_fragment(a00,0.f); wmma::fill_fragment(a01,0.f);
  wmma::fill_fragment(a10,0.f); wmma::fill_fragment(a11,0.f);
  stage_B(ws,192,0,0,smx,tid); cpcommit();
  for(int c=0;c<3;c++){
    int buf=c&1;
    if(c+1<3){ stage_B(ws,192,c+1,buf^1,smx,tid); cpcommit(); cpwaitg<1>(); }
    else cpwaitg<0>();
    __syncthreads();
    const __half* Ap; int astr;
    if(c==0){Ap=As; astr=SKA;} else {Ap=Hs+(c-1)*64; astr=SKH;}
    mma_chunk(Ap,astr,Bs+(size_t)(buf*2)*BPL,Bs+(size_t)(buf*2+1)*BPL,a00,a01,a10,a11,r0,cw);
    __syncthreads();
  }
  acc_store(D,a00,a01,a10,a11,r0,cw);
  __syncthreads();
  int C0=(tid>>6)*32,R=tid&63,node=base+R;
  if(node<NN){
    u32 hw[16];
#pragma unroll
    for(int j=0;j<16;j++)hw[j]=pack_h2(D[(size_t)R*DST+C0+2*j],D[(size_t)R*DST+C0+2*j+1]);
    uint4* oq=(uint4*)(g_q+(size_t)node*128+C0);
#pragma unroll
    for(int j=0;j<4;j++)oq[j]=((uint4*)hw)[j];
  }
  __syncthreads();
}
// K=128 GEMM, A from global (u) or Hs, into D_MID
template<int AHS>
__device__ __forceinline__ void gemm128_mid(int woff,const __half* p0,unsigned char* smx,int tid,int base){
  __half* As=(__half*)(smx+AS_OFF);
  __half* Bs=(__half*)(smx+BS_OFF);
  __half* Hs=(__half*)(smx+HS_OFF);
  float* D=(float*)(smx+DMID_OFF);
  const __half* ws=g_wimg+woff;
  int wid=tid>>5;
  int r0=(wid&1)*32, cw=(wid>>1)*32;
  FragC a00,a01,a10,a11;
  wmma::fill_fragment(a00,0.f); wmma::fill_fragment(a01,0.f);
  wmma::fill_fragment(a10,0.f); wmma::fill_fragment(a11,0.f);
  stage_B(ws,128,0,0,smx,tid);
  if(!AHS) stage_Ag(p0,128,0,0,smx,tid,base);
  cpcommit();
  stage_B(ws,128,1,1,smx,tid);
  if(!AHS) stage_Ag(p0,128,1,1,smx,tid,base);
  cpcommit();
  for(int c=0;c<2;c++){
    if(c==0) cpwaitg<1>(); else cpwaitg<0>();
    __syncthreads();
    const __half* Ap; int astr;
    if(AHS){Ap=Hs+c*64; astr=SKH;} else {Ap=As+(size_t)c*APL; astr=SKA;}
    mma_chunk(Ap,astr,Bs+(size_t)(c*2)*BPL,Bs+(size_t)(c*2+1)*BPL,a00,a01,a10,a11,r0,cw);
    __syncthreads();
  }
  acc_store(D,a00,a01,a10,a11,r0,cw);
  __syncthreads();
}

// fused: encoder + GEMM1 layer0
__global__ void __launch_bounds__(256,2) k_encg1(const float* __restrict__ b_in){
  extern __shared__ unsigned char smx[];
  int tid=threadIdx.x;
  int base=blockIdx.x*TM;
  int wid=tid>>5;
  int r0=(wid&1)*32, cw=(wid>>1)*32;
  __half* As=(__half*)(smx+AS_OFF);
  __half* Bs=(__half*)(smx+BS_OFF);
  float* D=(float*)(smx+DMID_OFF);
  stage_B(g_wimg,64,0,0,smx,tid);
  stage_Ag(g_xf,64,0,0,smx,tid,base);
  cpcommit(); cpwaitg<0>();
  __syncthreads();
  {
    FragC a00,a01,a10,a11;
    wmma::fill_fragment(a00,0.f); wmma::fill_fragment(a01,0.f);
    wmma::fill_fragment(a10,0.f); wmma::fill_fragment(a11,0.f);
    mma_chunk(As,SKA,Bs,Bs+BPL,a00,a01,a10,a11,r0,cw);
    __syncthreads();
    acc_store(D,a00,a01,a10,a11,r0,cw);
    __syncthreads();
  }
  epi_to_Hs<0>(smx,b_in,nullptr,nullptr,tid);
  stage_Ag(g_xf,64,0,0,smx,tid,base);   // restage x; committed with gemm1's first stage_B
  gemm1_to_q(16384,smx,tid,base);
}

// fused: GEMM2 layer l + GEMM1 layer l+1
__global__ void __launch_bounds__(256,2) k_g2g1(int woff2,int woff1,
    const float* __restrict__ b2,const float* __restrict__ lg,const float* __restrict__ lb){
  extern __shared__ unsigned char smx[];
  int tid=threadIdx.x;
  int base=blockIdx.x*TM;
  gemm128_mid<0>(woff2,g_uf,smx,tid,base);
  epi_to_Hs<1>(smx,b2,lg,lb,tid);
  stage_Ag(g_xf,64,0,0,smx,tid,base);
  gemm1_to_q(woff1,smx,tid,base);
}

// fused: GEMM2 layer2 + graphemb(LN+pool) + nodeout(LN+decoder)
__global__ void __launch_bounds__(256,2) k_g2fin(int woff2,
    const float* __restrict__ b2,const float* __restrict__ lg2,const float* __restrict__ lb2,
    const int* __restrict__ bidx,
    const float* __restrict__ gb,const float* __restrict__ glg,const float* __restrict__ glb,
    const float* __restrict__ ob,const float* __restrict__ lfg,const float* __restrict__ lfb,
    const float* __restrict__ x,
    const float* __restrict__ dW1,const float* __restrict__ db1,
    const float* __restrict__ dW2,const float* __restrict__ db2,
    const float* __restrict__ dW3,const float* __restrict__ db3,
    float* __restrict__ outp){
  extern __shared__ unsigned char smx[];
  int tid=threadIdx.x,lane=tid&31,wid=tid>>5;
  int base=blockIdx.x*TM;
  int* sbid=(int*)smx;
  float* sr1=(float*)(smx+512); float* sr2=(float*)(smx+1536);
  __half* Hs=(__half*)(smx+HS_OFF);
  if(tid<TM){int nd=base+tid; sbid[tid]=(nd<NN)?bidx[nd]:-1;}
  gemm128_mid<0>(woff2,g_uf,smx,tid,base);
  epi_to_Hs<1>(smx,b2,lg2,lb2,tid);
  // graphemb: A=Hs
  gemm128_mid<1>(262144,nullptr,smx,tid,base);
  {
    float* Dm=(float*)(smx+DMID_OFF);
    int C0=(tid>>6)*32,R=tid&63;
    float v[32]; float s=0.f,s2=0.f;
#pragma unroll
    for(int j=0;j<32;j++){v[j]=fmaxf(Dm[(size_t)R*DST+C0+j]+gb[C0+j],0.f); s+=v[j]; s2+=v[j]*v[j];}
    sr1[(tid>>6)*64+R]=s; sr2[(tid>>6)*64+R]=s2;
    __syncthreads();
    s=sr1[R]+sr1[64+R]+sr1[128+R]+sr1[192+R];
    s2=sr2[R]+sr2[64+R]+sr2[128+R]+sr2[192+R];
    float mu=s*(1.f/128.f), var=fmaxf(s2*(1.f/128.f)-mu*mu,0.f), rs=rsqrtf(var+1e-5f);
#pragma unroll
    for(int j=0;j<32;j++)Dm[(size_t)R*DST+C0+j]=(v[j]-mu)*rs*glg[C0+j]+glb[C0+j];
    __syncthreads();
    if(tid<128){
      int col=tid; float a=0.f; int cur=-1;
      for(int r=0;r<TM;r++){
        int bi=sbid[r];
        if(bi!=cur){ if(cur>=0)atomicAdd(&g_gsum[cur*128+col],a); a=0.f; cur=bi; }
        if(bi>=0)a+=Dm[(size_t)r*DST+col];
      }
      if(cur>=0)atomicAdd(&g_gsum[cur*128+col],a);
    }
    __syncthreads();
  }
  // nodeout: A=Hs
  gemm128_mid<1>(294912,nullptr,smx,tid,base);
  {
    float* Dm=(float*)(smx+DMID_OFF);
    int C0=(tid>>6)*32,R=tid&63;
    float v[32]; float s=0.f,s2=0.f;
#pragma unroll
    for(int j=0;j<32;j++){v[j]=fmaxf(Dm[(size_t)R*DST+C0+j]+ob[C0+j],0.f); s+=v[j]; s2+=v[j]*v[j];}
    sr1[(tid>>6)*64+R]=s; sr2[(tid>>6)*64+R]=s2;
    __syncthreads();
    s=sr1[R]+sr1[64+R]+sr1[128+R]+sr1[192+R];
    s2=sr2[R]+sr2[64+R]+sr2[128+R]+sr2[192+R];
    float mu=s*(1.f/128.f), var=fmaxf(s2*(1.f/128.f)-mu*mu,0.f), rs=rsqrtf(var+1e-5f);
#pragma unroll
    for(int j=0;j<32;j++)Dm[(size_t)R*DST+C0+j]=(v[j]-mu)*rs*lfg[C0+j]+lfb[C0+j];
    // decoder: xsh (fp32 x tile) into Hs region (dead), dsh in Bs region
    float* xsh=(float*)(smx+HS_OFF);
    float* dsh=(float*)(smx+BS_OFF);
    for(int i=tid;i<4096;i+=256){int r=i>>6,k=i&63;int nd=base+r;xsh[i]=(nd<NN)?x[(size_t)nd*64+k]:0.f;}
    for(int i=tid;i<6144;i+=256)dsh[DS_DW1+i]=dW1[i];
    if(tid<32)dsh[DS_DB1+tid]=db1[tid];
    if(tid<256)dsh[DS_DW2+tid]=dW2[tid];
    if(tid<8){dsh[DS_DB2+tid]=db2[tid];dsh[DS_DW3+tid]=dW3[tid];}
    if(tid==0)dsh[DS_DB3]=db3[0];
    __syncthreads();
    int j=lane, rr0=wid*8;
    for(int i=0;i<8;i++){
      int row=rr0+i, nd=base+row;
      float s1=dsh[DS_DB1+j];
      const float* xr=xsh+(size_t)row*64;
      const float* nr=Dm+(size_t)row*DST;
#pragma unroll 4
      for(int k=0;k<64;k++)s1=fmaf(xr[k],dsh[DS_DW1+k*32+j],s1);
#pragma unroll 4
      for(int k=0;k<128;k++)s1=fmaf(nr[k],dsh[DS_DW1+(64+k)*32+j],s1);
      s1=fmaxf(s1,0.f);
      float t2[8];
#pragma unroll
      for(int m=0;m<8;m++)t2[m]=s1*dsh[DS_DW2+j*8+m];
#pragma unroll
      for(int o=16;o>0;o>>=1)
#pragma unroll
        for(int m=0;m<8;m++)t2[m]+=__shfl_xor_sync(~0u,t2[m],o);
      float out=dsh[DS_DB3];
#pragma unroll
      for(int m=0;m<8;m++)out=fmaf(fmaxf(t2[m]+dsh[DS_DB2+m],0.f),dsh[DS_DW3+m],out);
      if(j==0&&nd<NN)outp[nd]=out;
    }
  }
}

// ---- graph-level MLP ----
__device__ __forceinline__ int lbound(const int* __restrict__ a,int n,int v){
  int lo=0,hi=n;
  while(lo<hi){int m=(lo+hi)>>1; if(a[m]<v)lo=m+1; else hi=m;}
  return lo;
}
__global__ void k_gmlp(const int* __restrict__ bidx,
    const float* __restrict__ gW1,const float* __restrict__ gb1,
    const float* __restrict__ gW2,const float* __restrict__ gb2,
    const float* __restrict__ gW3,const float* __restrict__ gb3,
    float* __restrict__ outp){
  int tid=threadIdx.x,lane=tid&31;
  int g=blockIdx.x*8+(tid>>5);
  int lo=lbound(bidx,NN,g),hi=lbound(bidx,NN,g+1);
  float inv=1.f/fmaxf((float)(hi-lo),1.f);
  float s1=gb1[lane];
  for(int k=0;k<128;k++)s1=fmaf(g_gsum[g*128+k]*inv,gW1[k*32+lane],s1);
  s1=fmaxf(s1,0.f);
  float t2[8];
#pragma unroll
  for(int m=0;m<8;m++)t2[m]=s1*gW2[lane*8+m];
#pragma unroll
  for(int o=16;o>0;o>>=1)
#pragma unroll
    for(int m=0;m<8;m++)t2[m]+=__shfl_xor_sync(~0u,t2[m],o);
  float out=gb3[0];
#pragma unroll
  for(int m=0;m<8;m++)out=fmaf(fmaxf(t2[m]+gb2[m],0.f),gW3[m],out);
  if(lane==0)outp[NN+g]=out;
}

extern "C" void kernel_launch(void* const* d_in,const int* in_sizes,int n_in,
                              void* d_out,int out_size){
  (void)in_sizes;(void)n_in;(void)out_size;
  const float* x   =(const float*)d_in[0];
  const int*   ei  =(const int*)  d_in[1];
  const int*   bidx=(const int*)  d_in[2];
  const float* W_in=(const float*)d_in[3];
  const float* b_in=(const float*)d_in[4];
  const float* eps =(const float*)d_in[5];
  const float* mW1 =(const float*)d_in[6];
  const float* mb1 =(const float*)d_in[7];
  const float* mW2 =(const float*)d_in[8];
  const float* mb2 =(const float*)d_in[9];
  const float* lng =(const float*)d_in[10];
  const float* lnb =(const float*)d_in[11];
  const float* oW  =(const float*)d_in[12];
  const float* ob  =(const float*)d_in[13];
  const float* lfg =(const float*)d_in[14];
  const float* lfb =(const float*)d_in[15];
  const float* gW  =(const float*)d_in[16];
  const float* gb  =(const float*)d_in[17];
  const float* glg =(const float*)d_in[18];
  const float* glb =(const float*)d_in[19];
  const float* dW1 =(const float*)d_in[20];
  const float* db1 =(const float*)d_in[21];
  const float* dW2 =(const float*)d_in[22];
  const float* db2 =(const float*)d_in[23];
  const float* dW3 =(const float*)d_in[24];
  const float* db3 =(const float*)d_in[25];
  const float* gW1 =(const float*)d_in[26];
  const float* gb1 =(const float*)d_in[27];
  const float* gW2 =(const float*)d_in[28];
  const float* gb2 =(const float*)d_in[29];
  const float* gW3 =(const float*)d_in[30];
  const float* gb3 =(const float*)d_in[31];
  float* outp=(float*)d_out;

  const int NG=(NN+TM-1)/TM;   // 1563
  cudaFuncSetAttribute((const void*)k_encg1,cudaFuncAttributeMaxDynamicSharedMemorySize,SM_TOT);
  cudaFuncSetAttribute((const void*)k_g2g1, cudaFuncAttributeMaxDynamicSharedMemorySize,SM_TOT);
  cudaFuncSetAttribute((const void*)k_g2fin,cudaFuncAttributeMaxDynamicSharedMemorySize,SM_TOT);

  // fork/join: CSR build runs on a side stream concurrent with prepw+encg1
  cudaStream_t s2;
  cudaStreamCreateWithFlags(&s2,cudaStreamNonBlocking);
  cudaEvent_t evF,evJ;
  cudaEventCreateWithFlags(&evF,cudaEventDisableTiming);
  cudaEventCreateWithFlags(&evJ,cudaEventDisableTiming);

  k_prepx<<<12500,256>>>(x);                 // splits x, zeroes g_deg/g_gsum
  cudaEventRecord(evF,0);
  cudaStreamWaitEvent(s2,evF,0);
  // branch B (side stream): CSR build
  k_hist<<<6250,256,0,s2>>>(ei);
  k_scan1<<<98,1024,0,s2>>>();
  k_scan2<<<1,128,0,s2>>>();
  k_scan3<<<98,1024,0,s2>>>();
  k_fill<<<6250,256,0,s2>>>(ei);
  cudaEventRecord(evJ,s2);
  // branch A (main stream): weights + encoder/GEMM1
  k_prepw<<<640,256>>>(W_in,mW1,mW2,gW,oW);
  k_encg1<<<NG,256,SM_TOT>>>(b_in);
  cudaStreamWaitEvent(0,evJ,0);              // join before first gather

  for(int l=0;l<2;l++){
    k_gatheru<<<12500,256>>>(eps,l,mb1+l*128);
    k_g2g1<<<NG,256,SM_TOT>>>(163840+l*32768,16384+(l+1)*49152,
        mb2+l*128,lng+l*128,lnb+l*128);
  }
  k_gatheru<<<12500,256>>>(eps,2,mb1+256);
  k_g2fin<<<NG,256,SM_TOT>>>(163840+2*32768,mb2+256,lng+256,lnb+256,bidx,
      gb,glg,glb,ob,lfg,lfb,x,dW1,db1,dW2,db2,dW3,db3,outp);
  k_gmlp<<<32,256>>>(bidx,gW1,gb1,gW2,gb2,gW3,gb3,outp);
}

// round 16
// speedup vs baseline: 1.0184x; 1.0017x over previous
#include <cuda_runtime.h>
#include <cuda_fp16.h>
#include <mma.h>

#define NN 100000
#define EE 1600000
#define BB 256
typedef unsigned long long u64;
typedef unsigned int u32;
using namespace nvcuda;

// ---- static scratch ----
__device__ __align__(16) __half g_xf[NN*64];
__device__ __align__(16) __half g_uf[NN*128];
__device__ __align__(16) __half g_q[NN*128];
__device__ __align__(16) __half g_wimg[327680];
__device__ float g_gsum[BB*128];
__device__ int g_deg[NN], g_rowptr[NN+1], g_cursor[NN], g_col[EE];
__device__ int g_bsum[128], g_boff[128];

__device__ __forceinline__ u32 pack_h2(float a,float b){
  __half2 h=__floats2half2_rn(a,b); return *(u32*)&h;
}
__device__ __forceinline__ void cpa16(void* dst,const void* src){
  u32 d=(u32)__cvta_generic_to_shared(dst);
  asm volatile("cp.async.cg.shared.global [%0],[%1],16;"::"r"(d),"l"(src));
}
__device__ __forceinline__ void cpcommit(){ asm volatile("cp.async.commit_group;":::"memory"); }
template<int N> __device__ __forceinline__ void cpwaitg(){ asm volatile("cp.async.wait_group %0;"::"n"(N):"memory"); }

// ---- CSR ----
__global__ void k_hist(const int* __restrict__ ei){int e=blockIdx.x*blockDim.x+threadIdx.x; if(e<EE)atomicAdd(&g_deg[ei[EE+e]],1);}
__global__ void k_scan1(){
  __shared__ int ws[32];
  int tid=threadIdx.x,lane=tid&31,wid=tid>>5;
  int i=blockIdx.x*1024+tid;
  int v=(i<NN)?g_deg[i]:0;
  int x=v;
#pragma unroll
  for(int o=16;o>0;o>>=1)x+=__shfl_xor_sync(~0u,x,o);
  if(lane==0)ws[wid]=x;
  __syncthreads();
  if(tid==0){int s=0;
#pragma unroll
    for(int w=0;w<32;w++)s+=ws[w];
    g_bsum[blockIdx.x]=s;}
}
__global__ void k_scan2(){
  __shared__ int ws[4];
  int tid=threadIdx.x,lane=tid&31,wid=tid>>5;
  int v=(tid<98)?g_bsum[tid]:0;
  int x=v;
#pragma unroll
  for(int o=1;o<32;o<<=1){int t=__shfl_up_sync(~0u,x,o); if(lane>=o)x+=t;}
  if(lane==31)ws[wid]=x;
  __syncthreads();
  int add=0;
  for(int w=0;w<wid;w++)add+=ws[w];
  if(tid<98)g_boff[tid]=add+x-v;
  if(tid==0)g_rowptr[NN]=EE;
}
__global__ void k_scan3(){
  __shared__ int ws[32];
  int tid=threadIdx.x,lane=tid&31,wid=tid>>5;
  int i=blockIdx.x*1024+tid;
  int v=(i<NN)?g_deg[i]:0;
  int x=v;
#pragma unroll
  for(int o=1;o<32;o<<=1){int t=__shfl_up_sync(~0u,x,o); if(lane>=o)x+=t;}
  if(lane==31)ws[wid]=x;
  __syncthreads();
  if(wid==0){int y=ws[lane];
#pragma unroll
    for(int o=1;o<32;o<<=1){int t=__shfl_up_sync(~0u,y,o); if(lane>=o)y+=t;} ws[lane]=y;}
  __syncthreads();
  if(i<NN){
    int ex=g_boff[blockIdx.x]+x-v+((wid>0)?ws[wid-1]:0);
    g_rowptr[i]=ex; g_cursor[i]=ex;
  }
}
__global__ void k_fill(const int* __restrict__ ei){
  int e=blockIdx.x*blockDim.x+threadIdx.x;
  if(e<EE){int d=ei[EE+e]; int p=atomicAdd(&g_cursor[d],1); g_col[p]=ei[e];}
}

// ---- merged prep: split x to fp16, zero g_deg/g_gsum, build W images ----
__global__ void k_prep(const float* __restrict__ x,
                       const float* __restrict__ Win,const float* __restrict__ W1,
                       const float* __restrict__ W2,const float* __restrict__ gW,
                       const float* __restrict__ oW){
  int i=blockIdx.x*blockDim.x+threadIdx.x;
  if(i<NN*32){
    float2 v=((const float2*)x)[i];
    ((u32*)g_xf)[i]=pack_h2(v.x,v.y);
    if(i<NN)g_deg[i]=0;
    if(i<BB*128)g_gsum[i]=0.f;
    return;
  }
  int gid=i-NN*32;
  if(gid>=163840)return;
  const float* src; int idx,K; __half* img;
  if(gid<8192){src=Win;idx=gid;K=64;img=g_wimg;}
  else if(gid<81920){int t=gid-8192;int l=t/24576;idx=t%24576;K=192;src=W1+l*24576;img=g_wimg+16384+l*49152;}
  else if(gid<131072){int t=gid-81920;int l=t/16384;idx=t%16384;K=128;src=W2+l*16384;img=g_wimg+163840+l*32768;}
  else if(gid<147456){idx=gid-131072;K=128;src=gW;img=g_wimg+262144;}
  else {idx=gid-147456;K=128;src=oW;img=g_wimg+294912;}
  float w=src[idx];
  __half h=__float2half_rn(w);
  __half l=__float2half_rn(w-__half2float(h));
  img[idx]=h; img[K*128+idx]=l;
}

// ---- fused gather + GIN pre-act: u = relu((1+eps)q + sum_nbr q + b1) -> fp16 (4-way MLP) ----
__global__ void k_gatheru(const float* __restrict__ eps,int layer,const float* __restrict__ b1){
  int w=(blockIdx.x*blockDim.x+threadIdx.x)>>5, lane=threadIdx.x&31;
  if(w>=NN)return;
  float e1=1.f+eps[layer];
  int s=g_rowptr[w],t=g_rowptr[w+1];
  float4 a0=make_float4(0,0,0,0),a1=a0,a2=a0,a3=a0;
  int e=s;
  auto ld4=[&](int nb)->float4{
    uint2 r=*(const uint2*)(g_q+(size_t)nb*128+lane*4);
    float2 f0=__half22float2(*(__half2*)&r.x);
    float2 f1=__half22float2(*(__half2*)&r.y);
    return make_float4(f0.x,f0.y,f1.x,f1.y);
  };
  for(;e+4<=t;e+=4){
    float4 v0=ld4(g_col[e]),v1=ld4(g_col[e+1]),v2=ld4(g_col[e+2]),v3=ld4(g_col[e+3]);
    a0.x+=v0.x;a0.y+=v0.y;a0.z+=v0.z;a0.w+=v0.w;
    a1.x+=v1.x;a1.y+=v1.y;a1.z+=v1.z;a1.w+=v1.w;
    a2.x+=v2.x;a2.y+=v2.y;a2.z+=v2.z;a2.w+=v2.w;
    a3.x+=v3.x;a3.y+=v3.y;a3.z+=v3.z;a3.w+=v3.w;
  }
  for(;e<t;e++){
    float4 v=ld4(g_col[e]);
    a0.x+=v.x;a0.y+=v.y;a0.z+=v.z;a0.w+=v.w;
  }
  a0.x+=a1.x+a2.x+a3.x; a0.y+=a1.y+a2.y+a3.y;
  a0.z+=a1.z+a2.z+a3.z; a0.w+=a1.w+a2.w+a3.w;
  float4 qo=ld4(w);
  float4 bv=*(const float4*)(b1+lane*4);
  float u0=fmaxf(fmaf(e1,qo.x,a0.x)+bv.x,0.f);
  float u1=fmaxf(fmaf(e1,qo.y,a0.y)+bv.y,0.f);
  float u2=fmaxf(fmaf(e1,qo.z,a0.z)+bv.z,0.f);
  float u3=fmaxf(fmaf(e1,qo.w,a0.w)+bv.w,0.f);
  *(uint2*)(g_uf+(size_t)w*128+lane*4)=make_uint2(pack_h2(u0,u1),pack_h2(u2,u3));
}

// ---- fused GEMM kernels: 64-row tiles, 256 threads, 2 CTAs/SM ----
#define AS_OFF 4096
#define BS_OFF 22528
#define HS_OFF 92160
#define SM_TOT 109568
#define DMID_OFF (BS_OFF+34816)
#define SKA 72
#define SKH 136
#define SNB 136
#define DST 132
#define TM 64
#define APL 4608
#define BPL 8704
#define DS_DW1 0
#define DS_DB1 6144
#define DS_DW2 6176
#define DS_DB2 6432
#define DS_DW3 6440
#define DS_DB3 6448

using FragA=wmma::fragment<wmma::matrix_a,16,16,16,__half,wmma::row_major>;
using FragB=wmma::fragment<wmma::matrix_b,16,16,16,__half,wmma::row_major>;
using FragC=wmma::fragment<wmma::accumulator,16,16,16,float>;

__device__ __forceinline__ void mma_chunk(const __half* Ap,int astr,const __half* Bh,const __half* Bl,
    FragC&a00,FragC&a01,FragC&a10,FragC&a11,int r0,int cw){
#pragma unroll
  for(int kc=0;kc<4;kc++){
    FragA ah0,ah1;
    wmma::load_matrix_sync(ah0,Ap+(size_t)r0*astr+kc*16,astr);
    wmma::load_matrix_sync(ah1,Ap+(size_t)(r0+16)*astr+kc*16,astr);
    FragB bh0,bh1,bl0,bl1;
    wmma::load_matrix_sync(bh0,Bh+(size_t)(kc*16)*SNB+cw,SNB);
    wmma::load_matrix_sync(bh1,Bh+(size_t)(kc*16)*SNB+cw+16,SNB);
    wmma::load_matrix_sync(bl0,Bl+(size_t)(kc*16)*SNB+cw,SNB);
    wmma::load_matrix_sync(bl1,Bl+(size_t)(kc*16)*SNB+cw+16,SNB);
    wmma::mma_sync(a00,ah0,bh0,a00); wmma::mma_sync(a00,ah0,bl0,a00);
    wmma::mma_sync(a01,ah0,bh1,a01); wmma::mma_sync(a01,ah0,bl1,a01);
    wmma::mma_sync(a10,ah1,bh0,a10); wmma::mma_sync(a10,ah1,bl0,a10);
    wmma::mma_sync(a11,ah1,bh1,a11); wmma::mma_sync(a11,ah1,bl1,a11);
  }
}
__device__ __forceinline__ void acc_store(float* D,FragC&a00,FragC&a01,FragC&a10,FragC&a11,int r0,int cw){
  wmma::store_matrix_sync(D+(size_t)r0*DST+cw,a00,DST,wmma::mem_row_major);
  wmma::store_matrix_sync(D+(size_t)r0*DST+cw+16,a01,DST,wmma::mem_row_major);
  wmma::store_matrix_sync(D+(size_t)(r0+16)*DST+cw,a10,DST,wmma::mem_row_major);
  wmma::store_matrix_sync(D+(size_t)(r0+16)*DST+cw+16,a11,DST,wmma::mem_row_major);
}
__device__ __forceinline__ void stage_B(const __half* ws,int KT,int c,int buf,unsigned char* smx,int tid){
  __half* Bs=(__half*)(smx+BS_OFF);
  for(int i=tid;i<2048;i+=256){
    int pl=i>>10,j=i&1023,kk=j>>4,u=j&15;
    cpa16(Bs+(size_t)(buf*2+pl)*BPL+kk*SNB+u*8,
          ws+(size_t)pl*KT*128+(size_t)(c*64+kk)*128+u*8);
  }
}
__device__ __forceinline__ void stage_Ag(const __half* p0,int K0,int c,int buf,unsigned char* smx,int tid,int base){
  __half* As=(__half*)(smx+AS_OFF);
  for(int i=tid;i<512;i+=256){
    int row=i>>3,u=i&7;
    int gc=c*64+u*8,node=base+row;
    __half* dst=As+(size_t)buf*APL+row*SKA+u*8;
    if(node<NN) cpa16(dst,p0+(size_t)node*K0+gc);
    else *(uint4*)dst=make_uint4(0,0,0,0);
  }
}
template<int MODE>
__device__ __forceinline__ void epi_to_Hs(unsigned char* smx,const float* bias,const float* lg,const float* lb,int tid){
  float* D=(float*)(smx+DMID_OFF);
  float* sr1=(float*)(smx+512); float* sr2=(float*)(smx+1536);
  __half* Hs=(__half*)(smx+HS_OFF);
  int C0=(tid>>6)*32,R=tid&63;
  float v[32];
  u32 hw[16];
  if(MODE==0){
#pragma unroll
    for(int j=0;j<32;j++)v[j]=fmaxf(D[(size_t)R*DST+C0+j]+bias[C0+j],0.f);
#pragma unroll
    for(int j=0;j<16;j++)hw[j]=pack_h2(v[2*j],v[2*j+1]);
  }else{
    float s=0.f,s2=0.f;
#pragma unroll
    for(int j=0;j<32;j++){v[j]=D[(size_t)R*DST+C0+j]+bias[C0+j]; s+=v[j]; s2+=v[j]*v[j];}
    sr1[(tid>>6)*64+R]=s; sr2[(tid>>6)*64+R]=s2;
    __syncthreads();
    s=sr1[R]+sr1[64+R]+sr1[128+R]+sr1[192+R];
    s2=sr2[R]+sr2[64+R]+sr2[128+R]+sr2[192+R];
    float mu=s*(1.f/128.f), var=fmaxf(s2*(1.f/128.f)-mu*mu,0.f), rs=rsqrtf(var+1e-5f);
#pragma unroll
    for(int j=0;j<16;j++){
      float n0=(v[2*j]-mu)*rs*lg[C0+2*j]+lb[C0+2*j];
      float n1=(v[2*j+1]-mu)*rs*lg[C0+2*j+1]+lb[C0+2*j+1];
      n0=(n0>0.f)?n0:expm1f(n0);
      n1=(n1>0.f)?n1:expm1f(n1);
      hw[j]=pack_h2(n0,n1);
    }
  }
  uint4* oh=(uint4*)(Hs+(size_t)R*SKH+C0);
#pragma unroll
  for(int j=0;j<4;j++)oh[j]=((uint4*)hw)[j];
  __syncthreads();
}
// GEMM1 (K=192): A chunk0 = As buf0 (x), chunks 1,2 = Hs. D -> g_q
__device__ __forceinline__ void gemm1_to_q(int woff,unsigned char* smx,int tid,int base){
  __half* As=(__half*)(smx+AS_OFF);
  __half* Bs=(__half*)(smx+BS_OFF);
  __half* Hs=(__half*)(smx+HS_OFF);
  float* D=(float*)(smx+AS_OFF);
  const __half* ws=g_wimg+woff;
  int wid=tid>>5;
  int r0=(wid&1)*32, cw=(wid>>1)*32;
  FragC a00,a01,a10,a11;
  wmma::fill_fragment(a00,0.f); wmma::fill_fragment(a01,0.f);
  wmma::fill_fragment(a10,0.f); wmma::fill_fragment(a11,0.f);
  stage_B(ws,192,0,0,smx,tid); cpcommit();
  for(int c=0;c<3;c++){
    int buf=c&1;
    if(c+1<3){ stage_B(ws,192,c+1,buf^1,smx,tid); cpcommit(); cpwaitg<1>(); }
    else cpwaitg<0>();
    __syncthreads();
    const __half* Ap; int astr;
    if(c==0){Ap=As; astr=SKA;} else {Ap=Hs+(c-1)*64; astr=SKH;}
    mma_chunk(Ap,astr,Bs+(size_t)(buf*2)*BPL,Bs+(size_t)(buf*2+1)*BPL,a00,a01,a10,a11,r0,cw);
    __syncthreads();
  }
  acc_store(D,a00,a01,a10,a11,r0,cw);
  __syncthreads();
  int C0=(tid>>6)*32,R=tid&63,node=base+R;
  if(node<NN){
    u32 hw[16];
#pragma unroll
    for(int j=0;j<16;j++)hw[j]=pack_h2(D[(size_t)R*DST+C0+2*j],D[(size_t)R*DST+C0+2*j+1]);
    uint4* oq=(uint4*)(g_q+(size_t)node*128+C0);
#pragma unroll
    for(int j=0;j<4;j++)oq[j]=((uint4*)hw)[j];
  }
  __syncthreads();
}
// K=128 GEMM, A from global (u) or Hs, into D_MID
template<int AHS>
__device__ __forceinline__ void gemm128_mid(int woff,const __half* p0,unsigned char* smx,int tid,int base){
  __half* As=(__half*)(smx+AS_OFF);
  __half* Bs=(__half*)(smx+BS_OFF);
  __half* Hs=(__half*)(smx+HS_OFF);
  float* D=(float*)(smx+DMID_OFF);
  const __half* ws=g_wimg+woff;
  int wid=tid>>5;
  int r0=(wid&1)*32, cw=(wid>>1)*32;
  FragC a00,a01,a10,a11;
  wmma::fill_fragment(a00,0.f); wmma::fill_fragment(a01,0.f);
  wmma::fill_fragment(a10,0.f); wmma::fill_fragment(a11,0.f);
  stage_B(ws,128,0,0,smx,tid);
  if(!AHS) stage_Ag(p0,128,0,0,smx,tid,base);
  cpcommit();
  stage_B(ws,128,1,1,smx,tid);
  if(!AHS) stage_Ag(p0,128,1,1,smx,tid,base);
  cpcommit();
  for(int c=0;c<2;c++){
    if(c==0) cpwaitg<1>(); else cpwaitg<0>();
    __syncthreads();
    const __half* Ap; int astr;
    if(AHS){Ap=Hs+c*64; astr=SKH;} else {Ap=As+(size_t)c*APL; astr=SKA;}
    mma_chunk(Ap,astr,Bs+(size_t)(c*2)*BPL,Bs+(size_t)(c*2+1)*BPL,a00,a01,a10,a11,r0,cw);
    __syncthreads();
  }
  acc_store(D,a00,a01,a10,a11,r0,cw);
  __syncthreads();
}

// fused: encoder + GEMM1 layer0
__global__ void __launch_bounds__(256,2) k_encg1(const float* __restrict__ b_in){
  extern __shared__ unsigned char smx[];
  int tid=threadIdx.x;
  int base=blockIdx.x*TM;
  int wid=tid>>5;
  int r0=(wid&1)*32, cw=(wid>>1)*32;
  __half* As=(__half*)(smx+AS_OFF);
  __half* Bs=(__half*)(smx+BS_OFF);
  float* D=(float*)(smx+DMID_OFF);
  stage_B(g_wimg,64,0,0,smx,tid);
  stage_Ag(g_xf,64,0,0,smx,tid,base);
  cpcommit(); cpwaitg<0>();
  __syncthreads();
  {
    FragC a00,a01,a10,a11;
    wmma::fill_fragment(a00,0.f); wmma::fill_fragment(a01,0.f);
    wmma::fill_fragment(a10,0.f); wmma::fill_fragment(a11,0.f);
    mma_chunk(As,SKA,Bs,Bs+BPL,a00,a01,a10,a11,r0,cw);
    __syncthreads();
    acc_store(D,a00,a01,a10,a11,r0,cw);
    __syncthreads();
  }
  epi_to_Hs<0>(smx,b_in,nullptr,nullptr,tid);
  stage_Ag(g_xf,64,0,0,smx,tid,base);   // restage x; committed with gemm1's first stage_B
  gemm1_to_q(16384,smx,tid,base);
}

// fused: GEMM2 layer l + GEMM1 layer l+1
__global__ void __launch_bounds__(256,2) k_g2g1(int woff2,int woff1,
    const float* __restrict__ b2,const float* __restrict__ lg,const float* __restrict__ lb){
  extern __shared__ unsigned char smx[];
  int tid=threadIdx.x;
  int base=blockIdx.x*TM;
  gemm128_mid<0>(woff2,g_uf,smx,tid,base);
  epi_to_Hs<1>(smx,b2,lg,lb,tid);
  stage_Ag(g_xf,64,0,0,smx,tid,base);
  gemm1_to_q(woff1,smx,tid,base);
}

// fused: GEMM2 layer2 + graphemb(LN+pool) + nodeout(LN+decoder)
__global__ void __launch_bounds__(256,2) k_g2fin(int woff2,
    const float* __restrict__ b2,const float* __restrict__ lg2,const float* __restrict__ lb2,
    const int* __restrict__ bidx,
    const float* __restrict__ gb,const float* __restrict__ glg,const float* __restrict__ glb,
    const float* __restrict__ ob,const float* __restrict__ lfg,const float* __restrict__ lfb,
    const float* __restrict__ x,
    const float* __restrict__ dW1,const float* __restrict__ db1,
    const float* __restrict__ dW2,const float* __restrict__ db2,
    const float* __restrict__ dW3,const float* __restrict__ db3,
    float* __restrict__ outp){
  extern __shared__ unsigned char smx[];
  int tid=threadIdx.x,lane=tid&31,wid=tid>>5;
  int base=blockIdx.x*TM;
  int* sbid=(int*)smx;
  float* sr1=(float*)(smx+512); float* sr2=(float*)(smx+1536);
  __half* Hs=(__half*)(smx+HS_OFF);
  if(tid<TM){int nd=base+tid; sbid[tid]=(nd<NN)?bidx[nd]:-1;}
  gemm128_mid<0>(woff2,g_uf,smx,tid,base);
  epi_to_Hs<1>(smx,b2,lg2,lb2,tid);
  // graphemb: A=Hs
  gemm128_mid<1>(262144,nullptr,smx,tid,base);
  {
    float* Dm=(float*)(smx+DMID_OFF);
    int C0=(tid>>6)*32,R=tid&63;
    float v[32]; float s=0.f,s2=0.f;
#pragma unroll
    for(int j=0;j<32;j++){v[j]=fmaxf(Dm[(size_t)R*DST+C0+j]+gb[C0+j],0.f); s+=v[j]; s2+=v[j]*v[j];}
    sr1[(tid>>6)*64+R]=s; sr2[(tid>>6)*64+R]=s2;
    __syncthreads();
    s=sr1[R]+sr1[64+R]+sr1[128+R]+sr1[192+R];
    s2=sr2[R]+sr2[64+R]+sr2[128+R]+sr2[192+R];
    float mu=s*(1.f/128.f), var=fmaxf(s2*(1.f/128.f)-mu*mu,0.f), rs=rsqrtf(var+1e-5f);
#pragma unroll
    for(int j=0;j<32;j++)Dm[(size_t)R*DST+C0+j]=(v[j]-mu)*rs*glg[C0+j]+glb[C0+j];
    __syncthreads();
    if(tid<128){
      int col=tid; float a=0.f; int cur=-1;
      for(int r=0;r<TM;r++){
        int bi=sbid[r];
        if(bi!=cur){ if(cur>=0)atomicAdd(&g_gsum[cur*128+col],a); a=0.f; cur=bi; }
        if(bi>=0)a+=Dm[(size_t)r*DST+col];
      }
      if(cur>=0)atomicAdd(&g_gsum[cur*128+col],a);
    }
    __syncthreads();
  }
  // nodeout: A=Hs
  gemm128_mid<1>(294912,nullptr,smx,tid,base);
  {
    float* Dm=(float*)(smx+DMID_OFF);
    int C0=(tid>>6)*32,R=tid&63;
    float v[32]; float s=0.f,s2=0.f;
#pragma unroll
    for(int j=0;j<32;j++){v[j]=fmaxf(Dm[(size_t)R*DST+C0+j]+ob[C0+j],0.f); s+=v[j]; s2+=v[j]*v[j];}
    sr1[(tid>>6)*64+R]=s; sr2[(tid>>6)*64+R]=s2;
    __syncthreads();
    s=sr1[R]+sr1[64+R]+sr1[128+R]+sr1[192+R];
    s2=sr2[R]+sr2[64+R]+sr2[128+R]+sr2[192+R];
    float mu=s*(1.f/128.f), var=fmaxf(s2*(1.f/128.f)-mu*mu,0.f), rs=rsqrtf(var+1e-5f);
#pragma unroll
    for(int j=0;j<32;j++)Dm[(size_t)R*DST+C0+j]=(v[j]-mu)*rs*lfg[C0+j]+lfb[C0+j];
    // decoder: xsh (fp32 x tile) into Hs region (dead), dsh in Bs region
    float* xsh=(float*)(smx+HS_OFF);
    float* dsh=(float*)(smx+BS_OFF);
    for(int i=tid;i<4096;i+=256){int r=i>>6,k=i&63;int nd=base+r;xsh[i]=(nd<NN)?x[(size_t)nd*64+k]:0.f;}
    for(int i=tid;i<6144;i+=256)dsh[DS_DW1+i]=dW1[i];
    if(tid<32)dsh[DS_DB1+tid]=db1[tid];
    if(tid<256)dsh[DS_DW2+tid]=dW2[tid];
    if(tid<8){dsh[DS_DB2+tid]=db2[tid];dsh[DS_DW3+tid]=dW3[tid];}
    if(tid==0)dsh[DS_DB3]=db3[0];
    __syncthreads();
    int j=lane, rr0=wid*8;
    for(int i=0;i<8;i++){
      int row=rr0+i, nd=base+row;
      float s1=dsh[DS_DB1+j];
      const float* xr=xsh+(size_t)row*64;
      const float* nr=Dm+(size_t)row*DST;
#pragma unroll 4
      for(int k=0;k<64;k++)s1=fmaf(xr[k],dsh[DS_DW1+k*32+j],s1);
#pragma unroll 4
      for(int k=0;k<128;k++)s1=fmaf(nr[k],dsh[DS_DW1+(64+k)*32+j],s1);
      s1=fmaxf(s1,0.f);
      float t2[8];
#pragma unroll
      for(int m=0;m<8;m++)t2[m]=s1*dsh[DS_DW2+j*8+m];
#pragma unroll
      for(int o=16;o>0;o>>=1)
#pragma unroll
        for(int m=0;m<8;m++)t2[m]+=__shfl_xor_sync(~0u,t2[m],o);
      float out=dsh[DS_DB3];
#pragma unroll
      for(int m=0;m<8;m++)out=fmaf(fmaxf(t2[m]+dsh[DS_DB2+m],0.f),dsh[DS_DW3+m],out);
      if(j==0&&nd<NN)outp[nd]=out;
    }
  }
}

// ---- graph-level MLP ----
__device__ __forceinline__ int lbound(const int* __restrict__ a,int n,int v){
  int lo=0,hi=n;
  while(lo<hi){int m=(lo+hi)>>1; if(a[m]<v)lo=m+1; else hi=m;}
  return lo;
}
__global__ void k_gmlp(const int* __restrict__ bidx,
    const float* __restrict__ gW1,const float* __restrict__ gb1,
    const float* __restrict__ gW2,const float* __restrict__ gb2,
    const float* __restrict__ gW3,const float* __restrict__ gb3,
    float* __restrict__ outp){
  int tid=threadIdx.x,lane=tid&31;
  int g=blockIdx.x*8+(tid>>5);
  int lo=lbound(bidx,NN,g),hi=lbound(bidx,NN,g+1);
  float inv=1.f/fmaxf((float)(hi-lo),1.f);
  float s1=gb1[lane];
  for(int k=0;k<128;k++)s1=fmaf(g_gsum[g*128+k]*inv,gW1[k*32+lane],s1);
  s1=fmaxf(s1,0.f);
  float t2[8];
#pragma unroll
  for(int m=0;m<8;m++)t2[m]=s1*gW2[lane*8+m];
#pragma unroll
  for(int o=16;o>0;o>>=1)
#pragma unroll
    for(int m=0;m<8;m++)t2[m]+=__shfl_xor_sync(~0u,t2[m],o);
  float out=gb3[0];
#pragma unroll
  for(int m=0;m<8;m++)out=fmaf(fmaxf(t2[m]+gb2[m],0.f),gW3[m],out);
  if(lane==0)outp[NN+g]=out;
}

extern "C" void kernel_launch(void* const* d_in,const int* in_sizes,int n_in,
                              void* d_out,int out_size){
  (void)in_sizes;(void)n_in;(void)out_size;
  const float* x   =(const float*)d_in[0];
  const int*   ei  =(const int*)  d_in[1];
  const int*   bidx=(const int*)  d_in[2];
  const float* W_in=(const float*)d_in[3];
  const float* b_in=(const float*)d_in[4];
  const float* eps =(const float*)d_in[5];
  const float* mW1 =(const float*)d_in[6];
  const float* mb1 =(const float*)d_in[7];
  const float* mW2 =(const float*)d_in[8];
  const float* mb2 =(const float*)d_in[9];
  const float* lng =(const float*)d_in[10];
  const float* lnb =(const float*)d_in[11];
  const float* oW  =(const float*)d_in[12];
  const float* ob  =(const float*)d_in[13];
  const float* lfg =(const float*)d_in[14];
  const float* lfb =(const float*)d_in[15];
  const float* gW  =(const float*)d_in[16];
  const float* gb  =(const float*)d_in[17];
  const float* glg =(const float*)d_in[18];
  const float* glb =(const float*)d_in[19];
  const float* dW1 =(const float*)d_in[20];
  const float* db1 =(const float*)d_in[21];
  const float* dW2 =(const float*)d_in[22];
  const float* db2 =(const float*)d_in[23];
  const float* dW3 =(const float*)d_in[24];
  const float* db3 =(const float*)d_in[25];
  const float* gW1 =(const float*)d_in[26];
  const float* gb1 =(const float*)d_in[27];
  const float* gW2 =(const float*)d_in[28];
  const float* gb2 =(const float*)d_in[29];
  const float* gW3 =(const float*)d_in[30];
  const float* gb3 =(const float*)d_in[31];
  float* outp=(float*)d_out;

  const int NG=(NN+TM-1)/TM;   // 1563
  cudaFuncSetAttribute((const void*)k_encg1,cudaFuncAttributeMaxDynamicSharedMemorySize,SM_TOT);
  cudaFuncSetAttribute((const void*)k_g2g1, cudaFuncAttributeMaxDynamicSharedMemorySize,SM_TOT);
  cudaFuncSetAttribute((const void*)k_g2fin,cudaFuncAttributeMaxDynamicSharedMemorySize,SM_TOT);

  // fork/join: CSR build on side stream concurrent with encg1
  cudaStream_t s2;
  cudaStreamCreateWithFlags(&s2,cudaStreamNonBlocking);
  cudaEvent_t evF,evJ;
  cudaEventCreateWithFlags(&evF,cudaEventDisableTiming);
  cudaEventCreateWithFlags(&evJ,cudaEventDisableTiming);

  k_prep<<<13140,256>>>(x,W_in,mW1,mW2,gW,oW);  // x split + zeroing + W images
  cudaEventRecord(evF,0);
  cudaStreamWaitEvent(s2,evF,0);
  // branch B (side stream): CSR build
  k_hist<<<6250,256,0,s2>>>(ei);
  k_scan1<<<98,1024,0,s2>>>();
  k_scan2<<<1,128,0,s2>>>();
  k_scan3<<<98,1024,0,s2>>>();
  k_fill<<<6250,256,0,s2>>>(ei);
  cudaEventRecord(evJ,s2);
  // branch A (main stream): encoder + GEMM1 l0
  k_encg1<<<NG,256,SM_TOT>>>(b_in);
  cudaStreamWaitEvent(0,evJ,0);              // join before first gather

  for(int l=0;l<2;l++){
    k_gatheru<<<12500,256>>>(eps,l,mb1+l*128);
    k_g2g1<<<NG,256,SM_TOT>>>(163840+l*32768,16384+(l+1)*49152,
        mb2+l*128,lng+l*128,lnb+l*128);
  }
  k_gatheru<<<12500,256>>>(eps,2,mb1+256);
  k_g2fin<<<NG,256,SM_TOT>>>(163840+2*32768,mb2+256,lng+256,lnb+256,bidx,
      gb,glg,glb,ob,lfg,lfb,x,dW1,db1,dW2,db2,dW3,db3,outp);
  k_gmlp<<<32,256>>>(bidx,gW1,gb1,gW2,gb2,gW3,gb3,outp);
}